// round 6
// baseline (speedup 1.0000x reference)
#include <cuda_runtime.h>

#define NB 4
#define NC 21
#define HH 512
#define WW 512
#define PH 171
#define OH 169
#define NCCH 84
#define PP (PH*PH)
#define LLN (OH*OH)
#define BANDS 5
#define MSZ 192
#define ALPHA 5e-4f

__device__ float    g_pr[NCCH*PP];
__device__ unsigned g_lab[NB*PP];
__device__ float    g_mpart[NCCH*BANDS*MSZ];
__device__ float    g_mred[NCCH*MSZ];
__device__ float    g_ce[NB*PH];
__device__ int      g_cnt[NB*PH];

__device__ __forceinline__ float ftanh(float x){float r;asm("tanh.approx.f32 %0,%1;":"=f"(r):"f"(x));return r;}

// ============ K1: CE + sigmoid/clip + 3x3 stride-3 maxpool + label bits ====
__global__ __launch_bounds__(512) void k_fused(const float* __restrict__ score,
                                               const int*   __restrict__ tg)
{
    __shared__ float    sp[NC*WW];
    __shared__ unsigned slab[WW];
    __shared__ float    wce[16];
    __shared__ int      wcnt[16];
    __shared__ int      s_is64;

    const int oy = blockIdx.x, n = blockIdx.y, x = threadIdx.x;

    if (x == 0) {
        int is64 = 1;
        #pragma unroll
        for (int i = 0; i < 32; i++) if (tg[2*i+1] != 0) is64 = 0;
        s_is64 = is64;
    }
    __syncthreads();
    const bool is64 = (s_is64 != 0);
    const long long* tg64 = (const long long*)tg;

    float vpool[NC];
    #pragma unroll
    for (int c = 0; c < NC; c++) vpool[c] = -1e30f;
    unsigned labbits = 0;
    float ce = 0.0f; int cnt = 0;

    const int r0 = 3*oy - 1;
    #pragma unroll
    for (int k = 0; k < 3; k++) {
        int r = r0 + k;
        if (r < 0 || r >= HH) continue;
        int pix = (n*HH + r)*WW + x;
        int t = is64 ? (int)tg64[pix] : tg[pix];
        bool mask21 = (t >= 0 && t < NC);
        bool valid  = (t != 255);
        const float* bp = score + ((size_t)(n*NC)*HH + r)*WW + x;

        float arr[NC];
        float m = -1e30f, xt = 0.0f;
        #pragma unroll
        for (int c = 0; c < NC; c++) {
            float v = __ldg(bp + (size_t)c*(HH*WW));
            arr[c] = v;
            m = fmaxf(m, v);
            if (c == t) xt = v;
        }
        float s = 0.0f;
        #pragma unroll
        for (int c = 0; c < NC; c++) {
            float v = arr[c];
            s += __expf(v - m);
            float sg  = fmaf(ftanh(0.5f*v), 0.5f, 0.5f);
            float val = mask21 ? fminf(fmaxf(sg, 1e-6f), 1.0f) : 1e-6f;
            vpool[c] = fmaxf(vpool[c], val);
        }
        if (valid) { ce += (m + __logf(s)) - xt; cnt++; }
        if (mask21) labbits |= (1u << t);
    }

    #pragma unroll
    for (int c = 0; c < NC; c++) sp[c*WW + x] = vpool[c];
    slab[x] = labbits;

    #pragma unroll
    for (int o = 16; o; o >>= 1) {
        ce  += __shfl_xor_sync(0xffffffffu, ce, o);
        cnt += __shfl_xor_sync(0xffffffffu, cnt, o);
    }
    if ((x & 31) == 0) { wce[x >> 5] = ce; wcnt[x >> 5] = cnt; }
    __syncthreads();
    if (x == 0) {
        float s = 0.f; int cc = 0;
        #pragma unroll
        for (int i = 0; i < 16; i++) { s += wce[i]; cc += wcnt[i]; }
        g_ce[n*PH + oy] = s; g_cnt[n*PH + oy] = cc;
    }

    for (int idx = x; idx < NC*PH; idx += 512) {
        int c = idx / PH, ox = idx - c*PH;
        int c0 = 3*ox - 1;
        float pm = -1e30f; unsigned ob = 0;
        #pragma unroll
        for (int j = 0; j < 3; j++) {
            int cc = c0 + j;
            if (cc >= 0 && cc < WW) { pm = fmaxf(pm, sp[c*WW + cc]); ob |= slab[cc]; }
        }
        g_pr[((n*NC + c)*PH + oy)*PH + ox] = pm;
        if (c == 0) g_lab[(n*PH + oy)*PH + ox] = ob;
    }
}

// ============ K2: Gram moments of the 9 shifted crops (values - 0.5) =======
__global__ __launch_bounds__(384) void k_mom()
{
    __shared__ float wbuf[12][81];
    const int nc   = blockIdx.x;
    const int band = blockIdx.y;
    const int n = nc / NC, c = nc % NC;
    const int tid  = threadIdx.x;
    const int grp  = tid >> 7;
    const int gt   = tid & 127;
    const int warp = tid >> 5, lane = tid & 31;

    float red[81];
    #pragma unroll
    for (int j = 0; j < 81; j++) red[j] = 0.0f;

    const int row = band*34 + gt/3;
    const int seg = gt - (gt/3)*3;
    const bool active = (gt < 102) && (row < OH);

    if (active) {
        const int xs = seg*57;
        const int xe = xs + ((seg == 2) ? 55 : 57);
        const float*    pr0 = g_pr  + nc*PP + row*PH;
        const unsigned* la0 = g_lab + n*PP  + row*PH;

        if (grp == 0) {                      // S_lp full 9x9
            float La[3][3], Pr[3][3];        // [col_age][row_off]
            #pragma unroll
            for (int a = 0; a < 2; a++)
                #pragma unroll
                for (int r = 0; r < 3; r++) {
                    Pr[a][r] = __ldg(pr0 + r*PH + xs + a) - 0.5f;
                    La[a][r] = ((__ldg(la0 + r*PH + xs + a) >> c) & 1u) ? 0.5f : -0.5f;
                }
            for (int xx = xs; xx < xe; xx++) {
                #pragma unroll
                for (int r = 0; r < 3; r++) {
                    Pr[2][r] = __ldg(pr0 + r*PH + xx + 2) - 0.5f;
                    La[2][r] = ((__ldg(la0 + r*PH + xx + 2) >> c) & 1u) ? 0.5f : -0.5f;
                }
                #pragma unroll
                for (int d = 0; d < 9; d++) {
                    float lv = La[d % 3][d / 3];
                    #pragma unroll
                    for (int e = 0; e < 9; e++)
                        red[d*9+e] = fmaf(lv, Pr[e % 3][e / 3], red[d*9+e]);
                }
                #pragma unroll
                for (int r = 0; r < 3; r++) {
                    Pr[0][r] = Pr[1][r]; Pr[1][r] = Pr[2][r];
                    La[0][r] = La[1][r]; La[1][r] = La[2][r];
                }
            }
        } else if (grp == 1) {               // S_pp tri(45) + s_pr(9)
            float Pr[3][3];
            #pragma unroll
            for (int a = 0; a < 2; a++)
                #pragma unroll
                for (int r = 0; r < 3; r++)
                    Pr[a][r] = __ldg(pr0 + r*PH + xs + a) - 0.5f;
            for (int xx = xs; xx < xe; xx++) {
                #pragma unroll
                for (int r = 0; r < 3; r++)
                    Pr[2][r] = __ldg(pr0 + r*PH + xx + 2) - 0.5f;
                float v[9];
                #pragma unroll
                for (int d = 0; d < 9; d++) v[d] = Pr[d % 3][d / 3];
                int k = 0;
                #pragma unroll
                for (int d = 0; d < 9; d++) {
                    red[45+d] += v[d];
                    #pragma unroll
                    for (int e = d; e < 9; e++) { red[k] = fmaf(v[d], v[e], red[k]); k++; }
                }
                #pragma unroll
                for (int r = 0; r < 3; r++) { Pr[0][r] = Pr[1][r]; Pr[1][r] = Pr[2][r]; }
            }
        } else {                              // S_ll tri(45) + s_la(9)
            float La[3][3];
            #pragma unroll
            for (int a = 0; a < 2; a++)
                #pragma unroll
                for (int r = 0; r < 3; r++)
                    La[a][r] = ((__ldg(la0 + r*PH + xs + a) >> c) & 1u) ? 0.5f : -0.5f;
            for (int xx = xs; xx < xe; xx++) {
                #pragma unroll
                for (int r = 0; r < 3; r++)
                    La[2][r] = ((__ldg(la0 + r*PH + xx + 2) >> c) & 1u) ? 0.5f : -0.5f;
                float v[9];
                #pragma unroll
                for (int d = 0; d < 9; d++) v[d] = La[d % 3][d / 3];
                int k = 0;
                #pragma unroll
                for (int d = 0; d < 9; d++) {
                    red[45+d] += v[d];
                    #pragma unroll
                    for (int e = d; e < 9; e++) { red[k] = fmaf(v[d], v[e], red[k]); k++; }
                }
                #pragma unroll
                for (int r = 0; r < 3; r++) { La[0][r] = La[1][r]; La[1][r] = La[2][r]; }
            }
        }
    }

    #pragma unroll
    for (int j = 0; j < 81; j++) {
        float v = red[j];
        #pragma unroll
        for (int o = 16; o; o >>= 1) v += __shfl_xor_sync(0xffffffffu, v, o);
        if (lane == (j & 31)) wbuf[warp][j] = v;
    }
    __syncthreads();

    // layout: [0..80]=S_lp, [81..125]=S_pp tri, [126..134]=s_pr,
    //         [135..179]=S_ll tri, [180..188]=s_la
    if (tid < 189) {
        int g, lj;
        if      (tid < 81)  { g = 0; lj = tid; }
        else if (tid < 135) { g = 1; lj = tid - 81; }
        else                { g = 2; lj = tid - 135; }
        float s = wbuf[g*4+0][lj] + wbuf[g*4+1][lj] + wbuf[g*4+2][lj] + wbuf[g*4+3][lj];
        g_mpart[(nc*BANDS + band)*MSZ + tid] = s;
    }
}

// ============ K3: reduce + 9x9 linear algebra + final scalar ===============
#define TRI(d,e) ((d)*9 - (d)*((d)-1)/2 + (e)-(d))

__global__ __launch_bounds__(256) void k_final(float* __restrict__ out, int out_size)
{
    __shared__ float srmi[NCCH];
    __shared__ float rce[256];
    __shared__ int   rcn[256];
    const int tid = threadIdx.x;

    // band reduce (fixed order)
    for (int i = tid; i < NCCH*189; i += 256) {
        int nc = i / 189, j = i - nc*189;
        float s = 0.f;
        #pragma unroll
        for (int b = 0; b < BANDS; b++) s += g_mpart[(nc*BANDS + b)*MSZ + j];
        g_mred[nc*MSZ + j] = s;
    }

    // CE reduce (deterministic)
    float cs = 0.f; int cc = 0;
    for (int i = tid; i < NB*PH; i += 256) { cs += g_ce[i]; cc += g_cnt[i]; }
    rce[tid] = cs; rcn[tid] = cc;
    __syncthreads();
    for (int o = 128; o; o >>= 1) {
        if (tid < o) { rce[tid] += rce[tid+o]; rcn[tid] += rcn[tid+o]; }
        __syncthreads();
    }

    // per (n,c) RMI
    if (tid < NCCH) {
        const float* m = g_mred + tid*MSZ;
        const float invL = 1.0f / (float)LLN;
        float clp[81], cpp[45], cll[45], spr[9], sla[9];
        #pragma unroll
        for (int d = 0; d < 9; d++) { spr[d] = m[126+d]; sla[d] = m[180+d]; }
        int k = 0;
        for (int d = 0; d < 9; d++)
            for (int e = d; e < 9; e++) {
                cpp[k] = m[81+k]  - spr[d]*spr[e]*invL + (d==e ? ALPHA : 0.0f);
                cll[k] = m[135+k] - sla[d]*sla[e]*invL;
                k++;
            }
        for (int d = 0; d < 9; d++)
            for (int e = 0; e < 9; e++)
                clp[d*9+e] = m[d*9+e] - sla[d]*spr[e]*invL;

        // chol(cpp) in place (G[i][j] at TRI(j,i))
        for (int j = 0; j < 9; j++) {
            float s = cpp[TRI(j,j)];
            for (int q = 0; q < j; q++) { float g = cpp[TRI(q,j)]; s -= g*g; }
            float gjj = sqrtf(fmaxf(s, 1e-20f));
            cpp[TRI(j,j)] = gjj;
            float inv = 1.0f / gjj;
            for (int i = j+1; i < 9; i++) {
                float t = cpp[TRI(j,i)];
                for (int q = 0; q < j; q++) t -= cpp[TRI(q,i)]*cpp[TRI(q,j)];
                cpp[TRI(j,i)] = t*inv;
            }
        }
        // forward solve: Y = G^-1 Clp^T, Y[i][d] in clp[d*9+i]
        for (int d = 0; d < 9; d++)
            for (int i = 0; i < 9; i++) {
                float s = clp[d*9+i];
                for (int q = 0; q < i; q++) s -= cpp[TRI(q,i)]*clp[d*9+q];
                clp[d*9+i] = s / cpp[TRI(i,i)];
            }
        // M = Cll + alpha I - Y^T Y
        k = 0;
        for (int d = 0; d < 9; d++)
            for (int e = d; e < 9; e++) {
                float s = cll[k];
                for (int i = 0; i < 9; i++) s -= clp[d*9+i]*clp[e*9+i];
                if (d == e) s += ALPHA;
                cll[k] = s; k++;
            }
        // chol(M) + sum log diag
        float rmi = 0.0f;
        for (int j = 0; j < 9; j++) {
            float s = cll[TRI(j,j)];
            for (int q = 0; q < j; q++) { float g = cll[TRI(q,j)]; s -= g*g; }
            float gjj = sqrtf(fmaxf(s, 0.0f));
            cll[TRI(j,j)] = gjj;
            float inv = 1.0f / gjj;
            for (int i = j+1; i < 9; i++) {
                float t = cll[TRI(j,i)];
                for (int q = 0; q < j; q++) t -= cll[TRI(q,i)]*cll[TRI(q,j)];
                cll[TRI(j,i)] = t*inv;
            }
            rmi += logf(gjj + 1e-8f);
        }
        srmi[tid] = rmi;
    }
    __syncthreads();

    if (tid == 0) {
        float rs = 0.f;
        #pragma unroll
        for (int i = 0; i < NCCH; i++) rs += srmi[i];
        float normal = rce[0] / (float)rcn[0];
        float loss = 0.5f*normal + 0.5f*(rs / 36.0f);
        for (int i = 0; i < out_size; i++) out[i] = loss;
    }
}

extern "C" void kernel_launch(void* const* d_in, const int* in_sizes, int n_in,
                              void* d_out, int out_size)
{
    const float* score;
    const int*   tg;
    if (in_sizes[0] >= in_sizes[1]) { score = (const float*)d_in[0]; tg = (const int*)d_in[1]; }
    else                            { score = (const float*)d_in[1]; tg = (const int*)d_in[0]; }

    k_fused<<<dim3(PH, NB), 512>>>(score, tg);
    k_mom<<<dim3(NCCH, BANDS), 384>>>();
    k_final<<<1, 256>>>((float*)d_out, out_size);
}